// round 4
// baseline (speedup 1.0000x reference)
#include <cuda_runtime.h>

// LightGCN 3-layer propagation + batched lookup — Round 4.
// CSR gather with per-destination-side layer passes (each pass's working set
// fits the 126MB L2), streaming CSR loads, 8 lanes/node x 2 float4.

constexpr int N_USERS = 200000;
constexpr int N_ITEMS = 100000;
constexpr int N_EDGES = 1000000;
constexpr int NT      = N_USERS + N_ITEMS;
constexpr int DV      = 16;                  // 64 floats = 16 float4
constexpr int BATCH   = 8192;

constexpr int NU4 = N_USERS * DV;
constexpr int NI4 = N_ITEMS * DV;

constexpr int SCAN_TPB   = 256;
constexpr int SCAN_ELEMS = 8;
constexpr int SCAN_TILE  = SCAN_TPB * SCAN_ELEMS;
constexpr int NB         = (NT + SCAN_TILE - 1) / SCAN_TILE;

__device__ float4 g_u[3][NU4];
__device__ float4 g_i[3][NI4];
__device__ int    g_cnt[NT];
__device__ int    g_off[NT + 1];
__device__ int    g_cur[NT];
__device__ int    g_bsum[NB];
__device__ int2   g_csr[2 * N_EDGES];        // .x = src node, .y = weight bits

// ---------------- preprocessing ----------------

__global__ void k_zero_cnt() {
    int t = blockIdx.x * blockDim.x + threadIdx.x;
    if (t < NT) g_cnt[t] = 0;
}

__global__ void k_hist(const int* __restrict__ eu, const int* __restrict__ ei) {
    int e = blockIdx.x * blockDim.x + threadIdx.x;
    if (e >= N_EDGES) return;
    atomicAdd(&g_cnt[__ldg(eu + e)], 1);
    atomicAdd(&g_cnt[N_USERS + __ldg(ei + e)], 1);
}

__device__ __forceinline__ int block_exscan(int v, int tid, int* total) {
    __shared__ int wsum[8];
    __shared__ int sh_total;
    int lane = tid & 31, wid = tid >> 5;
    int x = v;
    #pragma unroll
    for (int o = 1; o < 32; o <<= 1) {
        int y = __shfl_up_sync(0xffffffffu, x, o);
        if (lane >= o) x += y;
    }
    if (lane == 31) wsum[wid] = x;
    __syncthreads();
    if (wid == 0) {
        int t8 = (lane < 8) ? wsum[lane] : 0;
        int s = t8;
        #pragma unroll
        for (int o = 1; o < 8; o <<= 1) {
            int y = __shfl_up_sync(0xffffffffu, s, o);
            if (lane >= o) s += y;
        }
        if (lane < 8) wsum[lane] = s - t8;
        if (lane == 7) sh_total = s;
    }
    __syncthreads();
    int excl = wsum[wid] + (x - v);
    *total = sh_total;
    return excl;
}

__global__ void k_scan1() {
    int tid = threadIdx.x;
    int base = blockIdx.x * SCAN_TILE + tid * SCAN_ELEMS;
    int vals[SCAN_ELEMS];
    if (base < NT) {
        int4 a = *(const int4*)&g_cnt[base];
        int4 b = *(const int4*)&g_cnt[base + 4];
        vals[0]=a.x; vals[1]=a.y; vals[2]=a.z; vals[3]=a.w;
        vals[4]=b.x; vals[5]=b.y; vals[6]=b.z; vals[7]=b.w;
    } else {
        #pragma unroll
        for (int k = 0; k < SCAN_ELEMS; k++) vals[k] = 0;
    }
    int tsum = 0;
    #pragma unroll
    for (int k = 0; k < SCAN_ELEMS; k++) tsum += vals[k];
    int total;
    int tbase = block_exscan(tsum, tid, &total);
    if (base < NT) {
        int run = tbase;
        int outv[SCAN_ELEMS];
        #pragma unroll
        for (int k = 0; k < SCAN_ELEMS; k++) { outv[k] = run; run += vals[k]; }
        *(int4*)&g_off[base]     = make_int4(outv[0], outv[1], outv[2], outv[3]);
        *(int4*)&g_off[base + 4] = make_int4(outv[4], outv[5], outv[6], outv[7]);
    }
    if (tid == 0) g_bsum[blockIdx.x] = total;
}

__global__ void k_scan2() {
    int tid = threadIdx.x;
    int v = (tid < NB) ? g_bsum[tid] : 0;
    int total;
    int e = block_exscan(v, tid, &total);
    if (tid < NB) g_bsum[tid] = e;
}

__global__ void k_scan3() {
    int t = blockIdx.x * blockDim.x + threadIdx.x;
    if (t < NT) {
        int v = g_off[t] + g_bsum[t / SCAN_TILE];
        g_off[t] = v;
        g_cur[t] = v;
    }
    if (t == 0) g_off[NT] = 2 * N_EDGES;
}

__global__ void k_permute(const int* __restrict__ eu, const int* __restrict__ ei,
                          const float* __restrict__ nrm) {
    int e = blockIdx.x * blockDim.x + threadIdx.x;
    if (e >= N_EDGES) return;
    int u = __ldg(eu + e);
    int i = __ldg(ei + e);
    int wbits = __float_as_int(__ldg(nrm + e));
    int s1 = atomicAdd(&g_cur[N_USERS + i], 1);
    g_csr[s1] = make_int2(u, wbits);
    int s2 = atomicAdd(&g_cur[u], 1);
    g_csr[s2] = make_int2(i, wbits);
}

// ---------------- propagation: one destination side, one layer ----------------
// 8 lanes per node; each lane handles float4 columns (lane) and (lane+8).

__global__ void k_layer_pass(const float4* __restrict__ src, float4* __restrict__ dst,
                             const int* __restrict__ offbase, int nnodes) {
    int t = blockIdx.x * blockDim.x + threadIdx.x;
    int n = t >> 3;
    int lane = t & 7;
    if (n >= nnodes) return;

    int beg = __ldg(&offbase[n]);
    int end = __ldg(&offbase[n + 1]);

    float4 a0 = make_float4(0.f,0.f,0.f,0.f), b0 = a0, a1 = a0, b1 = a0;

    int j = beg;
    for (; j + 1 < end; j += 2) {
        int2 p0 = __ldcs(&g_csr[j]);
        int2 p1 = __ldcs(&g_csr[j + 1]);
        float w0 = __int_as_float(p0.y);
        float w1 = __int_as_float(p1.y);
        const float4* r0 = src + (long long)p0.x * DV;
        const float4* r1 = src + (long long)p1.x * DV;
        float4 x0 = __ldg(r0 + lane);
        float4 y0 = __ldg(r0 + lane + 8);
        float4 x1 = __ldg(r1 + lane);
        float4 y1 = __ldg(r1 + lane + 8);
        a0.x += x0.x*w0; a0.y += x0.y*w0; a0.z += x0.z*w0; a0.w += x0.w*w0;
        b0.x += y0.x*w0; b0.y += y0.y*w0; b0.z += y0.z*w0; b0.w += y0.w*w0;
        a1.x += x1.x*w1; a1.y += x1.y*w1; a1.z += x1.z*w1; a1.w += x1.w*w1;
        b1.x += y1.x*w1; b1.y += y1.y*w1; b1.z += y1.z*w1; b1.w += y1.w*w1;
    }
    if (j < end) {
        int2 p0 = __ldcs(&g_csr[j]);
        float w0 = __int_as_float(p0.y);
        const float4* r0 = src + (long long)p0.x * DV;
        float4 x0 = __ldg(r0 + lane);
        float4 y0 = __ldg(r0 + lane + 8);
        a0.x += x0.x*w0; a0.y += x0.y*w0; a0.z += x0.z*w0; a0.w += x0.w*w0;
        b0.x += y0.x*w0; b0.y += y0.y*w0; b0.z += y0.z*w0; b0.w += y0.w*w0;
    }

    long long d = (long long)n * DV + lane;
    dst[d]     = make_float4(a0.x + a1.x, a0.y + a1.y, a0.z + a1.z, a0.w + a1.w);
    dst[d + 8] = make_float4(b0.x + b1.x, b0.y + b1.y, b0.z + b1.z, b0.w + b1.w);
}

// ---------------- final batched lookup ----------------

__global__ void k_gather(const float4* __restrict__ uf, const float4* __restrict__ itf,
                         const int* __restrict__ users, const int* __restrict__ pos,
                         const int* __restrict__ neg, float4* __restrict__ out) {
    int t = blockIdx.x * blockDim.x + threadIdx.x;
    const int total = 3 * BATCH * DV;
    if (t >= total) return;
    int sec  = t / (BATCH * DV);
    int rem  = t % (BATCH * DV);
    int r    = rem / DV;
    int lane = rem % DV;

    float4 acc;
    if (sec == 0) {
        int idx = __ldg(users + r) * DV + lane;
        float4 a = uf[idx], b = g_u[0][idx], c = g_u[1][idx], d = g_u[2][idx];
        acc = make_float4(a.x + b.x + c.x + d.x, a.y + b.y + c.y + d.y,
                          a.z + b.z + c.z + d.z, a.w + b.w + c.w + d.w);
    } else {
        int idx = ((sec == 1) ? __ldg(pos + r) : __ldg(neg + r)) * DV + lane;
        float4 a = itf[idx], b = g_i[0][idx], c = g_i[1][idx], d = g_i[2][idx];
        acc = make_float4(a.x + b.x + c.x + d.x, a.y + b.y + c.y + d.y,
                          a.z + b.z + c.z + d.z, a.w + b.w + c.w + d.w);
    }
    const float s = 0.25f;
    out[t] = make_float4(acc.x * s, acc.y * s, acc.z * s, acc.w * s);
}

extern "C" void kernel_launch(void* const* d_in, const int* in_sizes, int n_in,
                              void* d_out, int out_size) {
    const float4* user_feat = (const float4*)d_in[0];
    const float4* item_feat = (const float4*)d_in[1];
    const int*    edge_u    = (const int*)d_in[2];
    const int*    edge_i    = (const int*)d_in[3];
    const float*  nrm       = (const float*)d_in[4];
    const int*    users     = (const int*)d_in[5];
    const int*    pos       = (const int*)d_in[6];
    const int*    neg       = (const int*)d_in[7];
    float4*       out       = (float4*)d_out;

    const int TPB = 256;

    k_zero_cnt<<<(NT + TPB - 1) / TPB, TPB>>>();
    k_hist<<<(N_EDGES + TPB - 1) / TPB, TPB>>>(edge_u, edge_i);
    k_scan1<<<NB, SCAN_TPB>>>();
    k_scan2<<<1, SCAN_TPB>>>();
    k_scan3<<<(NT + TPB - 1) / TPB, TPB>>>();
    k_permute<<<(N_EDGES + TPB - 1) / TPB, TPB>>>(edge_u, edge_i, nrm);

    // g_off entries: users [0, N_USERS), items [N_USERS, NT)
    const int* off_u = nullptr;  // set via device symbol arithmetic below
    // We pass raw addresses of the device arrays (valid in device code context).

    for (int l = 0; l < 3; l++) {
        const float4* srcU = (l == 0) ? user_feat : (const float4*)0;  // placeholder
        (void)srcU;
        // item-dst pass: src = user-side h_{l-1}
        {
            int threads = N_ITEMS * 8;
            const float4* src;
            float4* dst;
            // obtain device pointers to the static arrays via a tiny trampoline:
            // g_u/g_i symbols are directly usable in device code; from host we
            // launch with an index and resolve inside the kernel instead.
            // -> simpler: use a dispatch kernel signature with layer int.
            (void)threads; (void)src; (void)dst;
        }
        break;
    }

    // NOTE: static __device__ arrays cannot be addressed from host without
    // cudaGetSymbolAddress (not graph-unsafe, but host-side). Instead use a
    // wrapper kernel that resolves pointers on device via layer/side ints.
    for (int l = 0; l < 3; l++) {
        // handled by k_layer_dispatch below
    }

    // Dispatch wrapper launches:
    extern __global__ void k_layer_item(const float4*, int);
    extern __global__ void k_layer_user(const float4*, int);
    for (int l = 0; l < 3; l++) {
        k_layer_item<<<(N_ITEMS * 8 + TPB - 1) / TPB, TPB>>>(user_feat, l);
        k_layer_user<<<(N_USERS * 8 + TPB - 1) / TPB, TPB>>>(item_feat, l);
    }

    const int gt_total = 3 * BATCH * DV;
    k_gather<<<(gt_total + TPB - 1) / TPB, TPB>>>(user_feat, item_feat, users, pos, neg, out);
}

// Wrapper kernels resolving static-array pointers in device code.
__global__ void k_layer_item(const float4* __restrict__ uf, int layer) {
    const float4* src = (layer == 0) ? uf : g_u[layer - 1];
    int t = blockIdx.x * blockDim.x + threadIdx.x;
    int n = t >> 3;
    int lane = t & 7;
    if (n >= N_ITEMS) return;

    int beg = __ldg(&g_off[N_USERS + n]);
    int end = __ldg(&g_off[N_USERS + n + 1]);

    float4 a0 = make_float4(0.f,0.f,0.f,0.f), b0 = a0, a1 = a0, b1 = a0;
    int j = beg;
    for (; j + 1 < end; j += 2) {
        int2 p0 = __ldcs(&g_csr[j]);
        int2 p1 = __ldcs(&g_csr[j + 1]);
        float w0 = __int_as_float(p0.y);
        float w1 = __int_as_float(p1.y);
        const float4* r0 = src + (long long)p0.x * DV;
        const float4* r1 = src + (long long)p1.x * DV;
        float4 x0 = __ldg(r0 + lane);
        float4 y0 = __ldg(r0 + lane + 8);
        float4 x1 = __ldg(r1 + lane);
        float4 y1 = __ldg(r1 + lane + 8);
        a0.x += x0.x*w0; a0.y += x0.y*w0; a0.z += x0.z*w0; a0.w += x0.w*w0;
        b0.x += y0.x*w0; b0.y += y0.y*w0; b0.z += y0.z*w0; b0.w += y0.w*w0;
        a1.x += x1.x*w1; a1.y += x1.y*w1; a1.z += x1.z*w1; a1.w += x1.w*w1;
        b1.x += y1.x*w1; b1.y += y1.y*w1; b1.z += y1.z*w1; b1.w += y1.w*w1;
    }
    if (j < end) {
        int2 p0 = __ldcs(&g_csr[j]);
        float w0 = __int_as_float(p0.y);
        const float4* r0 = src + (long long)p0.x * DV;
        float4 x0 = __ldg(r0 + lane);
        float4 y0 = __ldg(r0 + lane + 8);
        a0.x += x0.x*w0; a0.y += x0.y*w0; a0.z += x0.z*w0; a0.w += x0.w*w0;
        b0.x += y0.x*w0; b0.y += y0.y*w0; b0.z += y0.z*w0; b0.w += y0.w*w0;
    }
    long long d = (long long)n * DV + lane;
    g_i[layer][d]     = make_float4(a0.x + a1.x, a0.y + a1.y, a0.z + a1.z, a0.w + a1.w);
    g_i[layer][d + 8] = make_float4(b0.x + b1.x, b0.y + b1.y, b0.z + b1.z, b0.w + b1.w);
}

__global__ void k_layer_user(const float4* __restrict__ itf, int layer) {
    const float4* src = (layer == 0) ? itf : g_i[layer - 1];
    int t = blockIdx.x * blockDim.x + threadIdx.x;
    int n = t >> 3;
    int lane = t & 7;
    if (n >= N_USERS) return;

    int beg = __ldg(&g_off[n]);
    int end = __ldg(&g_off[n + 1]);

    float4 a0 = make_float4(0.f,0.f,0.f,0.f), b0 = a0, a1 = a0, b1 = a0;
    int j = beg;
    for (; j + 1 < end; j += 2) {
        int2 p0 = __ldcs(&g_csr[j]);
        int2 p1 = __ldcs(&g_csr[j + 1]);
        float w0 = __int_as_float(p0.y);
        float w1 = __int_as_float(p1.y);
        const float4* r0 = src + (long long)p0.x * DV;
        const float4* r1 = src + (long long)p1.x * DV;
        float4 x0 = __ldg(r0 + lane);
        float4 y0 = __ldg(r0 + lane + 8);
        float4 x1 = __ldg(r1 + lane);
        float4 y1 = __ldg(r1 + lane + 8);
        a0.x += x0.x*w0; a0.y += x0.y*w0; a0.z += x0.z*w0; a0.w += x0.w*w0;
        b0.x += y0.x*w0; b0.y += y0.y*w0; b0.z += y0.z*w0; b0.w += y0.w*w0;
        a1.x += x1.x*w1; a1.y += x1.y*w1; a1.z += x1.z*w1; a1.w += x1.w*w1;
        b1.x += y1.x*w1; b1.y += y1.y*w1; b1.z += y1.z*w1; b1.w += y1.w*w1;
    }
    if (j < end) {
        int2 p0 = __ldcs(&g_csr[j]);
        float w0 = __int_as_float(p0.y);
        const float4* r0 = src + (long long)p0.x * DV;
        float4 x0 = __ldg(r0 + lane);
        float4 y0 = __ldg(r0 + lane + 8);
        a0.x += x0.x*w0; a0.y += x0.y*w0; a0.z += x0.z*w0; a0.w += x0.w*w0;
        b0.x += y0.x*w0; b0.y += y0.y*w0; b0.z += y0.z*w0; b0.w += y0.w*w0;
    }
    long long d = (long long)n * DV + lane;
    g_u[layer][d]     = make_float4(a0.x + a1.x, a0.y + a1.y, a0.z + a1.z, a0.w + a1.w);
    g_u[layer][d + 8] = make_float4(b0.x + b1.x, b0.y + b1.y, b0.z + b1.z, b0.w + b1.w);
}